// round 7
// baseline (speedup 1.0000x reference)
#include <cuda_runtime.h>
#include <cuda_bf16.h>

#define NUM_BINS 32
#define NBINS2   (NUM_BINS * NUM_BINS)
#define NWARPS   8            // warps per CTA (256 threads)
#define EPS 1e-5f

// Zero-initialized device globals. Invariant: g_hist == 0 and g_done == 0 at
// kernel entry; the last CTA restores this before exit (deterministic replays).
__device__ unsigned int g_hist[NBINS2];
__device__ unsigned int g_done;

// Inputs are exact integers 0..255 stored as fp32. bin = rint(v/255*31).
// v*31/255 is never exactly k+0.5 (62v even vs 255(2k+1) odd), and the nearest
// tie distance is 1/510 >> fp32 error of v*fl(31/255) (~7e-6), so
// floor(v*c + 0.5) gives bit-identical bins to the reference at 2 instructions.
__device__ __forceinline__ int bin_of(float v) {
    const float c = 31.0f / 255.0f;
    return (int)__fmaf_rn(v, c, 0.5f);   // F2I truncation == floor (v >= 0)
}

__device__ __forceinline__ void accum(unsigned int* wh, int bin, int lane) {
    unsigned int peers = __match_any_sync(0xFFFFFFFFu, bin);
    // leader = lowest lane in the equal-bin group
    if ((peers & ((1u << lane) - 1u)) == 0u) {
        wh[bin] += __popc(peers);        // plain smem RMW: warp-private, race-free
    }
}

__device__ __forceinline__ void accum4(unsigned int* wh, float4 a, float4 b, int lane) {
    accum(wh, bin_of(a.x) * NUM_BINS + bin_of(b.x), lane);
    accum(wh, bin_of(a.y) * NUM_BINS + bin_of(b.y), lane);
    accum(wh, bin_of(a.z) * NUM_BINS + bin_of(b.z), lane);
    accum(wh, bin_of(a.w) * NUM_BINS + bin_of(b.w), lane);
}

__global__ void __launch_bounds__(256) lmi_fused_kernel(
    const float4* __restrict__ I4,
    const float4* __restrict__ J4,
    int n4,
    float inv_total,
    float* __restrict__ out)
{
    __shared__ unsigned int sh[NWARPS * NBINS2];   // 32 KB: per-warp private hists
    const int t    = threadIdx.x;
    const int lane = t & 31;
    unsigned int* wh = &sh[(t >> 5) * NBINS2];

    for (int k = t; k < NWARPS * NBINS2; k += blockDim.x) sh[k] = 0u;
    __syncthreads();

    // ---- Phase 1: histogram (2x unrolled grid-stride, 4 LDG.128 in flight) ----
    const int stride = gridDim.x * blockDim.x;
    int i = blockIdx.x * blockDim.x + t;
    for (; i + stride < n4; i += 2 * stride) {
        float4 a0 = __ldcs(&I4[i]);
        float4 b0 = __ldcs(&J4[i]);
        float4 a1 = __ldcs(&I4[i + stride]);
        float4 b1 = __ldcs(&J4[i + stride]);
        accum4(wh, a0, b0, lane);
        accum4(wh, a1, b1, lane);
    }
    if (i < n4) {
        float4 a0 = __ldcs(&I4[i]);
        float4 b0 = __ldcs(&J4[i]);
        accum4(wh, a0, b0, lane);
    }
    __syncthreads();

    // ---- Phase 2: CTA flush — sum warp hists, one global atomic per bin ----
    for (int k = t; k < NBINS2; k += blockDim.x) {
        unsigned int s = 0u;
        #pragma unroll
        for (int w = 0; w < NWARPS; w++) s += sh[w * NBINS2 + k];
        if (s) atomicAdd(&g_hist[k], s);
    }

    // ---- Phase 3: last CTA computes MI, writes out, resets state ----
    __shared__ bool is_last;
    __threadfence();
    if (t == 0) {
        unsigned int done = atomicAdd(&g_done, 1u);
        is_last = (done == gridDim.x - 1);
    }
    __syncthreads();
    if (!is_last) return;

    // Reuse sh as the epilogue workspace (all CTAs' private hists done).
    float* jp   = (float*)sh;                 // [NBINS2]
    float* rowp = (float*)&sh[NBINS2];        // [32]
    float* colp = (float*)&sh[NBINS2 + 32];   // [32]
    float* wsum = (float*)&sh[NBINS2 + 64];   // [NWARPS]

    #pragma unroll
    for (int u = 0; u < 4; u++) {
        int k = t + u * 256;
        unsigned int v = __ldcg(&g_hist[k]);  // bypass L1: atomics landed in L2
        jp[k] = (float)v * inv_total;
        g_hist[k] = 0u;                       // reset for next replay
    }
    if (t == 0) g_done = 0u;
    __syncthreads();

    if (t < NUM_BINS) {
        float s = 0.0f;
        #pragma unroll
        for (int c = 0; c < NUM_BINS; c++) s += jp[t * NUM_BINS + c];
        rowp[t] = s;
    } else if (t < 2 * NUM_BINS) {
        int c = t - NUM_BINS;
        float s = 0.0f;
        #pragma unroll
        for (int r = 0; r < NUM_BINS; r++) s += jp[r * NUM_BINS + c];
        colp[c] = s;
    }
    __syncthreads();

    float term = 0.0f;
    #pragma unroll
    for (int u = 0; u < 4; u++) {
        int b = t + u * 256;
        float p  = jp[b];
        float pi = rowp[b >> 5];
        float pj = colp[b & 31];
        term += p * (logf(p + EPS) - logf(pi + EPS) - logf(pj + EPS));
    }

    #pragma unroll
    for (int off = 16; off > 0; off >>= 1)
        term += __shfl_xor_sync(0xFFFFFFFFu, term, off);
    if (lane == 0) wsum[t >> 5] = term;
    __syncthreads();
    if (t < NWARPS) {
        float s = wsum[t];
        #pragma unroll
        for (int off = NWARPS / 2; off > 0; off >>= 1)
            s += __shfl_xor_sync((1u << NWARPS) - 1u, s, off);
        if (t == 0) {
            out[0] = 1.0f / (1.0f + expf(s));   // sigmoid(-mi)
        }
    }
}

extern "C" void kernel_launch(void* const* d_in, const int* in_sizes, int n_in,
                              void* d_out, int out_size)
{
    const float* I = (const float*)d_in[0];
    const float* J = (const float*)d_in[1];
    float* out = (float*)d_out;
    const int n  = in_sizes[0];   // 33,554,432
    const int n4 = n / 4;

    const int threads = 256;
    const int blocks  = 148 * 6;  // 888 CTAs, 6/SM (32KB smem each)
    lmi_fused_kernel<<<blocks, threads>>>((const float4*)I, (const float4*)J,
                                          n4, 1.0f / (float)n, out);
}

// round 8
// speedup vs baseline: 7.3319x; 7.3319x over previous
#include <cuda_runtime.h>
#include <cuda_bf16.h>

#define NUM_BINS 32
#define NBINS2   (NUM_BINS * NUM_BINS)
#define EPS 1e-5f

// Zero-initialized device globals. Invariant: g_hist == 0 and g_done == 0 at
// kernel entry; the last CTA restores this before exit (deterministic replays).
__device__ unsigned int g_hist[NBINS2];
__device__ unsigned int g_done;

// Inputs are exact integers 0..255 stored as fp32. bin = rint(v/255*31).
// v*31/255 is never exactly k+0.5 (62v is even, 255(2k+1) odd), and the
// nearest tie distance is 1/510 >> fp32 rounding error of v*fl(31/255)
// (~7e-6), so floor(v*c + 0.5) is bit-identical to the reference binning.
// Verified rel_err == 0.0 in round 7. Two instructions: FFMA + F2I.
__device__ __forceinline__ int bin_of(float v) {
    const float c = 31.0f / 255.0f;
    return (int)__fmaf_rn(v, c, 0.5f);   // F2I truncation == floor (v >= 0)
}

__device__ __forceinline__ void accum4(unsigned int* sh, float4 a, float4 b) {
    // ATOMS are fire-and-forget: no result dependency, 4 in flight per thread
    atomicAdd(&sh[bin_of(a.x) * NUM_BINS + bin_of(b.x)], 1u);
    atomicAdd(&sh[bin_of(a.y) * NUM_BINS + bin_of(b.y)], 1u);
    atomicAdd(&sh[bin_of(a.z) * NUM_BINS + bin_of(b.z)], 1u);
    atomicAdd(&sh[bin_of(a.w) * NUM_BINS + bin_of(b.w)], 1u);
}

__global__ void __launch_bounds__(256) lmi_fused_kernel(
    const float4* __restrict__ I4,
    const float4* __restrict__ J4,
    int n4,
    float inv_total,
    float* __restrict__ out)
{
    __shared__ unsigned int sh[NBINS2];   // 4 KB CTA-shared histogram
    const int t = threadIdx.x;

    #pragma unroll
    for (int k = t; k < NBINS2; k += 256) sh[k] = 0u;
    __syncthreads();

    // ---- Phase 1: histogram (2x unrolled grid-stride, 4 LDG.128 in flight) ----
    const int stride = gridDim.x * blockDim.x;
    int i = blockIdx.x * blockDim.x + t;
    for (; i + stride < n4; i += 2 * stride) {
        float4 a0 = __ldcs(&I4[i]);
        float4 b0 = __ldcs(&J4[i]);
        float4 a1 = __ldcs(&I4[i + stride]);
        float4 b1 = __ldcs(&J4[i + stride]);
        accum4(sh, a0, b0);
        accum4(sh, a1, b1);
    }
    if (i < n4) {
        float4 a0 = __ldcs(&I4[i]);
        float4 b0 = __ldcs(&J4[i]);
        accum4(sh, a0, b0);
    }
    __syncthreads();

    // ---- Phase 2: flush CTA histogram to global (spread REDG, 4/thread) ----
    #pragma unroll
    for (int k = t; k < NBINS2; k += 256) {
        unsigned int v = sh[k];
        if (v) atomicAdd(&g_hist[k], v);
    }

    // ---- Phase 3: last CTA computes MI, writes out, resets state ----
    __shared__ bool is_last;
    __threadfence();   // order flush atomics before counter
    if (t == 0) {
        unsigned int done = atomicAdd(&g_done, 1u);
        is_last = (done == gridDim.x - 1);
    }
    __syncthreads();
    if (!is_last) return;

    __shared__ float jp[NBINS2];
    __shared__ float rowp[NUM_BINS];
    __shared__ float colp[NUM_BINS];
    __shared__ float wsum[8];

    #pragma unroll
    for (int u = 0; u < 4; u++) {
        int k = t + u * 256;
        unsigned int v = __ldcg(&g_hist[k]);  // bypass L1: atomics landed in L2
        jp[k] = (float)v * inv_total;
        g_hist[k] = 0u;                       // reset invariant for next replay
    }
    if (t == 0) g_done = 0u;
    __syncthreads();

    if (t < NUM_BINS) {
        float s = 0.0f;
        #pragma unroll
        for (int c = 0; c < NUM_BINS; c++) s += jp[t * NUM_BINS + c];
        rowp[t] = s;
    } else if (t < 2 * NUM_BINS) {
        int c = t - NUM_BINS;
        float s = 0.0f;
        #pragma unroll
        for (int r = 0; r < NUM_BINS; r++) s += jp[r * NUM_BINS + c];
        colp[c] = s;
    }
    __syncthreads();

    float term = 0.0f;
    #pragma unroll
    for (int u = 0; u < 4; u++) {
        int b = t + u * 256;
        float p  = jp[b];
        float pi = rowp[b >> 5];
        float pj = colp[b & 31];
        term += p * (logf(p + EPS) - logf(pi + EPS) - logf(pj + EPS));
    }

    #pragma unroll
    for (int off = 16; off > 0; off >>= 1)
        term += __shfl_xor_sync(0xFFFFFFFFu, term, off);
    if ((t & 31) == 0) wsum[t >> 5] = term;
    __syncthreads();
    if (t < 8) {
        float s = wsum[t];
        #pragma unroll
        for (int off = 4; off > 0; off >>= 1)
            s += __shfl_xor_sync(0xFFu, s, off);
        if (t == 0) {
            out[0] = 1.0f / (1.0f + expf(s));   // sigmoid(-mi)
        }
    }
}

extern "C" void kernel_launch(void* const* d_in, const int* in_sizes, int n_in,
                              void* d_out, int out_size)
{
    const float* I = (const float*)d_in[0];
    const float* J = (const float*)d_in[1];
    float* out = (float*)d_out;
    const int n  = in_sizes[0];   // 33,554,432
    const int n4 = n / 4;

    const int threads = 256;
    const int blocks  = 148 * 8;  // 1184 CTAs, 8/SM (4 KB smem each)
    lmi_fused_kernel<<<blocks, threads>>>((const float4*)I, (const float4*)J,
                                          n4, 1.0f / (float)n, out);
}